// round 17
// baseline (speedup 1.0000x reference)
#include <cuda_runtime.h>
#include <cuda_fp16.h>
#include <cstdint>

// Problem constants (fixed by dataset): N=50000 nodes, E=1.6M edges, K=128 feat dim.
#define NODE_CAP 50048
#define EDGE_CAP 1700000
#define KDIM 128

// Scratch (no cudaMalloc allowed).
__device__ __align__(16) float  g_bufB[NODE_CAP * KDIM];  // gathered layer-1 (128-dim fp32)
__device__ __align__(16) __half g_h1[NODE_CAP * KDIM];    // layer-1 pre-agg features (fp16)
__device__ __align__(16) __half g_h2[NODE_CAP * 64];      // layer-2 pre-agg features (fp16, sO pre-applied)
__device__ __align__(16) float  g_W2f[KDIM * 64];         // W2 @ Wf
__device__ __align__(16) float  g_c2[64];                 // b2 @ Wf + bf
__device__ int   g_degO[NODE_CAP];
__device__ int   g_degI[NODE_CAP];
__device__ float g_sO[NODE_CAP];
__device__ float g_sI[NODE_CAP];
__device__ int   g_rowptr[NODE_CAP + 1];
__device__ int   g_cursor[NODE_CAP];
__device__ int   g_csr[EDGE_CAP];        // src indices grouped by dst

// ---------------------------------------------------------------------------
// Single-block prefix scan over deg_in -> row_ptr (exclusive) + cursors,
// PLUS the rsqrt scales (deg atomics completed with GEMM1, which runs first).
// ---------------------------------------------------------------------------
__global__ void scan_kernel(int n) {
    __shared__ int part[1024];
    int tid = threadIdx.x;
    int CH = (n + 1023) / 1024;
    int beg = tid * CH;
    int sum = 0;
#pragma unroll 4
    for (int i = 0; i < CH; i++) {
        int idx = beg + i;
        if (idx < n) sum += g_degI[idx];
    }
    part[tid] = sum;
    __syncthreads();
    for (int off = 1; off < 1024; off <<= 1) {
        int v = (tid >= off) ? part[tid - off] : 0;
        __syncthreads();
        part[tid] += v;
        __syncthreads();
    }
    int run = (tid == 0) ? 0 : part[tid - 1];
#pragma unroll 4
    for (int i = 0; i < CH; i++) {
        int idx = beg + i;
        if (idx < n) {
            int d = g_degI[idx];
            g_rowptr[idx] = run;
            g_cursor[idx] = run;
            run += d;
            g_sI[idx] = rsqrtf((float)max(d, 1));
            g_sO[idx] = rsqrtf((float)max(g_degO[idx], 1));
        }
    }
    if (tid == 1023) g_rowptr[n] = part[1023];
}

// ---------------------------------------------------------------------------
// Fill CSR (all blocks, 2 edges/thread) + fused side jobs in low blocks:
//   blocks [0,32):   W2f = W2 @ Wf  (128x64, one element/thread)
//   block  32:       c2 = b2 @ Wf + bf
//   blocks [33,33+3125): h1 prescale: h1[r][*] *= sO[r]  (one uint4 = 8 halfs
//                    per thread; 800K uint4 total). Removes the sO pointer-
//                    chase from gather128. Fill is latency-bound (issue ~3%),
//                    so the extra memory ops ride along nearly free.
// ---------------------------------------------------------------------------
__global__ void fill_kernel(const int* __restrict__ src, const int* __restrict__ dst,
                            const float* __restrict__ W2, const float* __restrict__ Wf,
                            const float* __restrict__ b2, const float* __restrict__ bf,
                            int E, int n) {
    int b = blockIdx.x;
    int tid = threadIdx.x;

    int i = (b * 256 + tid) * 2;
    if (i < E) {
        int d0 = dst[i], s0 = src[i];
        if (i + 1 < E) {
            int d1 = dst[i + 1], s1 = src[i + 1];
            int p0 = atomicAdd(&g_cursor[d0], 1);
            int p1 = atomicAdd(&g_cursor[d1], 1);
            g_csr[p0] = s0;
            g_csr[p1] = s1;
        } else {
            int p0 = atomicAdd(&g_cursor[d0], 1);
            g_csr[p0] = s0;
        }
    }

    if (b < 32) {                       // W2f
        int idx = b * 256 + tid;        // < 8192 = 128*64
        int r = idx >> 6;
        int c = idx & 63;
        float s = 0.f;
#pragma unroll 8
        for (int k = 0; k < KDIM; k++)
            s += __ldg(&W2[r * KDIM + k]) * __ldg(&Wf[k * 64 + c]);
        g_W2f[idx] = s;
    } else if (b == 32) {               // c2
        if (tid < 64) {
            float s = __ldg(&bf[tid]);
#pragma unroll 8
            for (int k = 0; k < KDIM; k++)
                s += __ldg(&b2[k]) * __ldg(&Wf[k * 64 + tid]);
            g_c2[tid] = s;
        }
    } else {                            // h1 prescale by sO[row]
        int idx = (b - 33) * 256 + tid; // uint4 index; row = idx/16
        if (idx < n * 16) {
            int r = idx >> 4;
            float so = g_sO[r];
            __half2 sh = __float2half2_rn(so);
            uint4* p = (uint4*)g_h1 + idx;
            uint4 v = *p;
            __half2* h = (__half2*)&v;
            h[0] = __hmul2(h[0], sh);
            h[1] = __hmul2(h[1], sh);
            h[2] = __hmul2(h[2], sh);
            h[3] = __hmul2(h[3], sh);
            *p = v;
        }
    }
}

// ---------------------------------------------------------------------------
// Pull aggregation, fp16 input (sO pre-applied), 128-dim rows:
//   B[w] = sum_{s in N_in(w)} h1s[s]
// Warp per dst node; lane l owns halfs [4l,4l+4). Inner loop: uniform csr LDG,
// one dependent 8B LDG, cvt, 4 FADD. Unroll-2 for MLP.
// ---------------------------------------------------------------------------
__global__ void gather128h_kernel(const uint2* __restrict__ H, float4* __restrict__ Out, int n) {
    int gt = blockIdx.x * blockDim.x + threadIdx.x;
    int w = gt >> 5;
    int l = gt & 31;
    if (w >= n) return;
    int j = g_rowptr[w];
    int end = g_rowptr[w + 1];
    float4 a0 = make_float4(0.f, 0.f, 0.f, 0.f);
    float4 a1 = make_float4(0.f, 0.f, 0.f, 0.f);
    for (; j + 2 <= end; j += 2) {
        int s0 = __ldg(&g_csr[j]);
        int s1 = __ldg(&g_csr[j + 1]);
        uint2 q0 = __ldg(&H[s0 * 32 + l]);
        uint2 q1 = __ldg(&H[s1 * 32 + l]);
        float2 x0 = __half22float2(*(__half2*)&q0.x);
        float2 y0 = __half22float2(*(__half2*)&q0.y);
        float2 x1 = __half22float2(*(__half2*)&q1.x);
        float2 y1 = __half22float2(*(__half2*)&q1.y);
        a0.x += x0.x; a0.y += x0.y; a0.z += y0.x; a0.w += y0.y;
        a1.x += x1.x; a1.y += x1.y; a1.z += y1.x; a1.w += y1.y;
    }
    if (j < end) {
        int s0 = __ldg(&g_csr[j]);
        uint2 q0 = __ldg(&H[s0 * 32 + l]);
        float2 x0 = __half22float2(*(__half2*)&q0.x);
        float2 y0 = __half22float2(*(__half2*)&q0.y);
        a0.x += x0.x; a0.y += x0.y; a0.z += y0.x; a0.w += y0.y;
    }
    Out[w * 32 + l] = make_float4(a0.x + a1.x, a0.y + a1.y, a0.z + a1.z, a0.w + a1.w);
}

// ---------------------------------------------------------------------------
// Pull aggregation, fp16 input (sO pre-applied by gemm2 epilogue), 64-dim,
// final epilogue fused:  out[w][c] = (sum h2s[s][c]) * sI[w] + c2[c]
// ---------------------------------------------------------------------------
__global__ void gather64h_kernel(const __half2* __restrict__ H, float2* __restrict__ Out, int n) {
    int gt = blockIdx.x * blockDim.x + threadIdx.x;
    int w = gt >> 5;
    int l = gt & 31;
    if (w >= n) return;
    int j = g_rowptr[w];
    int end = g_rowptr[w + 1];
    float2 a0 = make_float2(0.f, 0.f);
    float2 a1 = make_float2(0.f, 0.f);
    for (; j + 2 <= end; j += 2) {
        int s0 = __ldg(&g_csr[j]);
        int s1 = __ldg(&g_csr[j + 1]);
        float2 f0 = __half22float2(__ldg(&H[s0 * 32 + l]));
        float2 f1 = __half22float2(__ldg(&H[s1 * 32 + l]));
        a0.x += f0.x; a0.y += f0.y;
        a1.x += f1.x; a1.y += f1.y;
    }
    if (j < end) {
        int s0 = __ldg(&g_csr[j]);
        float2 f0 = __half22float2(__ldg(&H[s0 * 32 + l]));
        a0.x += f0.x; a0.y += f0.y;
    }
    float si = g_sI[w];
    float2 b = *(const float2*)&g_c2[l * 2];
    Out[w * 32 + l] = make_float2((a0.x + a1.x) * si + b.x, (a0.y + a1.y) * si + b.y);
}

// ---------------------------------------------------------------------------
// fp32 register-tiled GEMM: Ch[M,N] (fp16) = f(A[M,128]) @ W[128,N] [* sO]
//   MODE 0: a = A[r][k]; plain output              (layer 1; sO applied later)
//   MODE 1: a = max(A[r][k]*s_in[r] + bias[k], 0); output *= sO[r]  (layer 2)
// DEG=true additionally counts edge degrees with fire-and-forget REDs.
// ---------------------------------------------------------------------------
template <int N, int MODE, bool DEG>
__global__ void gemm_kernel(const float* __restrict__ A_src, const float* __restrict__ W,
                            const float* __restrict__ bias_in,
                            __half* __restrict__ Outh, int M,
                            const int* __restrict__ src, const int* __restrict__ dst, int E) {
    constexpr int BM = 64;
    extern __shared__ float smem[];
    float* Ws = smem;            // K * N
    float* As = smem + KDIM * N; // BM * K

    int tid = threadIdx.x;
    int m0 = blockIdx.x * BM;

    if (DEG) {
        int gid = blockIdx.x * blockDim.x + tid;
        int stride = gridDim.x * blockDim.x;
        for (int e = gid; e < E; e += stride) {
            atomicAdd(&g_degO[src[e]], 1);   // RED: no return value used
            atomicAdd(&g_degI[dst[e]], 1);
        }
    }

    for (int i = tid * 4; i < KDIM * N; i += 256 * 4) {
        *(float4*)&Ws[i] = *(const float4*)&W[i];
    }

    for (int i = tid; i < BM * KDIM / 4; i += 256) {
        int r = i >> 5;
        int kc = (i & 31) * 4;
        int gr = m0 + r;
        float4 v = make_float4(0.f, 0.f, 0.f, 0.f);
        if (gr < M) {
            v = *(const float4*)&A_src[gr * KDIM + kc];
            if (MODE == 1) {
                float si = g_sI[gr];
                float4 b = *(const float4*)&bias_in[kc];
                v.x = fmaxf(v.x * si + b.x, 0.f);
                v.y = fmaxf(v.y * si + b.y, 0.f);
                v.z = fmaxf(v.z * si + b.z, 0.f);
                v.w = fmaxf(v.w * si + b.w, 0.f);
            }
        }
        *(float4*)&As[r * KDIM + kc] = v;
    }
    __syncthreads();

    constexpr int CT = N / 4;        // 32 (N=128) or 16 (N=64)
    constexpr int RT = 256 / CT;     // 8 or 16
    constexpr int RPT = BM / RT;     // 8 or 4
    int ct = tid % CT;
    int rt = tid / CT;
    int c0 = ct * 4;
    int r0 = rt * RPT;

    float4 acc[RPT];
#pragma unroll
    for (int i = 0; i < RPT; i++) acc[i] = make_float4(0.f, 0.f, 0.f, 0.f);

#pragma unroll 4
    for (int k = 0; k < KDIM; k++) {
        float4 b = *(const float4*)&Ws[k * N + c0];
#pragma unroll
        for (int i = 0; i < RPT; i++) {
            float a = As[(r0 + i) * KDIM + k];
            acc[i].x += a * b.x;
            acc[i].y += a * b.y;
            acc[i].z += a * b.z;
            acc[i].w += a * b.w;
        }
    }

#pragma unroll
    for (int i = 0; i < RPT; i++) {
        int gr = m0 + r0 + i;
        if (gr < M) {
            float4 o = acc[i];
            if (MODE == 1) {
                float so = g_sO[gr];   // fold sO here so gather64 skips it
                o.x *= so; o.y *= so; o.z *= so; o.w *= so;
            }
            __half2 lo = __floats2half2_rn(o.x, o.y);
            __half2 hi = __floats2half2_rn(o.z, o.w);
            uint2 u;
            u.x = *(unsigned*)&lo;
            u.y = *(unsigned*)&hi;
            *(uint2*)&Outh[gr * N + c0] = u;
        }
    }
}

// ---------------------------------------------------------------------------
extern "C" void kernel_launch(void* const* d_in, const int* in_sizes, int n_in,
                              void* d_out, int out_size) {
    const float* X  = (const float*)d_in[0];
    const int* src  = (const int*)d_in[1];
    const int* dst  = (const int*)d_in[2];
    const float* W1 = (const float*)d_in[3];
    const float* b1 = (const float*)d_in[4];
    const float* W2 = (const float*)d_in[5];
    const float* b2 = (const float*)d_in[6];
    const float* Wf = (const float*)d_in[7];
    const float* bf = (const float*)d_in[8];
    float* out = (float*)d_out;

    int n = in_sizes[0] / KDIM;   // 50000
    int E = in_sizes[1];          // 1600000

    void *pB_, *pH1_, *pH2_, *pW2f_, *pDO_, *pDI_;
    cudaGetSymbolAddress(&pB_, g_bufB);
    cudaGetSymbolAddress(&pH1_, g_h1);
    cudaGetSymbolAddress(&pH2_, g_h2);
    cudaGetSymbolAddress(&pW2f_, g_W2f);
    cudaGetSymbolAddress(&pDO_, g_degO);
    cudaGetSymbolAddress(&pDI_, g_degI);

    const int smem128 = (KDIM * 128 + 64 * KDIM) * sizeof(float); // 96KB
    const int smem64  = (KDIM * 64  + 64 * KDIM) * sizeof(float); // 64KB
    cudaFuncSetAttribute(gemm_kernel<128, 0, true>, cudaFuncAttributeMaxDynamicSharedMemorySize, smem128);
    cudaFuncSetAttribute(gemm_kernel<64, 1, false>, cudaFuncAttributeMaxDynamicSharedMemorySize, smem64);

    int gemm_blocks  = (n + 63) / 64;                 // 782
    int agg_blocks   = (n * 32 + 255) / 256;          // 6250
    // fill needs: max(ceil(E/512)=3125 fill blocks, 33 + ceil(n*16/256)=3125+33 side blocks)
    int fill_blocks  = 33 + (n * 16 + 255) / 256;     // 3158 (covers both roles)

    // 1. zero degree counters
    cudaMemsetAsync(pDO_, 0, n * sizeof(int));
    cudaMemsetAsync(pDI_, 0, n * sizeof(int));

    // 2. layer-1 GEMM (plain X@W1 -> fp16) with degree atomics hidden inside
    gemm_kernel<128, 0, true><<<gemm_blocks, 256, smem128>>>(
        X, W1, nullptr, (__half*)pH1_, n, src, dst, E);

    // 3. rowptr scan (+ scales), then CSR fill (+ W2f/c2 + h1*=sO side jobs)
    scan_kernel<<<1, 1024>>>(n);
    fill_kernel<<<fill_blocks, 256>>>(src, dst, W2, Wf, b2, bf, E, n);

    // 4. aggregate layer 1 (h1 pre-scaled): B = sum h1s[s]
    gather128h_kernel<<<agg_blocks, 256>>>((const uint2*)pH1_, (float4*)pB_, n);

    // 5. layer-2 GEMM: h2 = (relu(B*sI + b1) @ W2f) * sO -> fp16
    gemm_kernel<64, 1, false><<<gemm_blocks, 256, smem64>>>(
        (const float*)pB_, (const float*)pW2f_, b1, (__half*)pH2_, n,
        nullptr, nullptr, 0);

    // 6. aggregate layer 2 (h2 pre-scaled) + final epilogue -> out
    gather64h_kernel<<<agg_blocks, 256>>>((const __half2*)pH2_, (float2*)out, n);
}